// round 2
// baseline (speedup 1.0000x reference)
#include <cuda_runtime.h>
#include <math.h>

#define BATCH 16
#define NMASK 6
#define HW 1089
#define DIM 512
#define NLBL 7
#define INV_T (1.0f/0.07f)
#define SEPM 2.0f
#define UNITH 0.1f

#define BM 128
#define BN 128
#define BK 32
#define SPAD 4
#define CTILES 9   // ceil(1089/128)

// ---- scratch (device globals: allocation-free) ----
__device__ float g_label_sums[BATCH][NLBL][DIM];
__device__ float g_cnt[BATCH][NLBL];
__device__ float g_q[BATCH][NLBL];
__device__ float g_supcon_sum[BATCH];
__device__ float g_anchor_cnt[BATCH];
__device__ int   g_active[BATCH * NMASK];
__device__ int   g_labels[BATCH * HW];
__device__ float g_rn2[BATCH * HW];

// ---------------------------------------------------------------------------
// prep: per-(b,m) mask channel sums -> active flags; zero atomic accumulators
// ---------------------------------------------------------------------------
__global__ void prep_kernel(const float* __restrict__ masks) {
    int blk = blockIdx.x;
    if (blk < BATCH * NMASK) {
        const float* m = masks + (size_t)blk * HW;
        float s = 0.f;
        for (int i = threadIdx.x; i < HW; i += blockDim.x) s += m[i];
        __shared__ float sh[256];
        sh[threadIdx.x] = s;
        __syncthreads();
        for (int o = 128; o > 0; o >>= 1) {
            if (threadIdx.x < o) sh[threadIdx.x] += sh[threadIdx.x + o];
            __syncthreads();
        }
        if (threadIdx.x == 0) g_active[blk] = (sh[0] > 0.f) ? 1 : 0;
    } else {
        if (threadIdx.x < BATCH) {
            g_supcon_sum[threadIdx.x] = 0.f;
            g_anchor_cnt[threadIdx.x] = 0.f;
        }
    }
}

// ---------------------------------------------------------------------------
// labels: per pixel, label = max over m of (m+1) where mask>0.5 & active
// ---------------------------------------------------------------------------
__global__ void labels_kernel(const float* __restrict__ masks) {
    int idx = blockIdx.x * blockDim.x + threadIdx.x;
    if (idx >= BATCH * HW) return;
    int b = idx / HW, n = idx - b * HW;
    const float* mb = masks + (size_t)b * NMASK * HW;
    int lbl = 0;
#pragma unroll
    for (int m = 0; m < NMASK; m++) {
        if (mb[(size_t)m * HW + n] > 0.5f && g_active[b * NMASK + m]) lbl = m + 1;
    }
    g_labels[idx] = lbl;
}

// ---------------------------------------------------------------------------
// rn2: per-pixel squared norm (one warp per pixel)
// ---------------------------------------------------------------------------
__global__ void rn2_kernel(const float* __restrict__ emb) {
    int w = (blockIdx.x * blockDim.x + threadIdx.x) >> 5;
    int lane = threadIdx.x & 31;
    if (w >= BATCH * HW) return;
    const float4* f = (const float4*)(emb + (size_t)w * DIM);
    float s = 0.f;
#pragma unroll
    for (int d4 = lane; d4 < DIM / 4; d4 += 32) {
        float4 v = f[d4];
        s += v.x * v.x + v.y * v.y + v.z * v.z + v.w * v.w;
    }
#pragma unroll
    for (int o = 16; o > 0; o >>= 1) s += __shfl_xor_sync(0xffffffffu, s, o);
    if (lane == 0) g_rn2[w] = s;
}

// ---------------------------------------------------------------------------
// centroids: per-image per-label feature sums, counts, sum of rn2
// one block per image, 512 threads (thread = dim)
// ---------------------------------------------------------------------------
__global__ void centroid_kernel(const float* __restrict__ emb) {
    int b = blockIdx.x;
    int t = threadIdx.x;
    const float* fb = emb + (size_t)b * HW * DIM;
    float acc[NLBL];
#pragma unroll
    for (int l = 0; l < NLBL; l++) acc[l] = 0.f;
    for (int n = 0; n < HW; n++) {
        int lbl = g_labels[b * HW + n];
        float v = fb[(size_t)n * DIM + t];
#pragma unroll
        for (int l = 0; l < NLBL; l++) acc[l] += (lbl == l) ? v : 0.f;
    }
#pragma unroll
    for (int l = 0; l < NLBL; l++) g_label_sums[b][l][t] = acc[l];
    if (t < NLBL) {
        float c = 0.f, q = 0.f;
        for (int n = 0; n < HW; n++) {
            if (g_labels[b * HW + n] == t) { c += 1.f; q += g_rn2[b * HW + n]; }
        }
        g_cnt[b][t] = c;
        g_q[b][t] = q;
    }
}

// ---------------------------------------------------------------------------
// supcon: fused Gram GEMM + streamed log-sum-exp epilogue.
// Block = 128 rows of one image. Loops over 9 column tiles of 128.
// Per row accumulate S (exp sum), P (positive logit sum), C (positive count).
// ---------------------------------------------------------------------------
__global__ __launch_bounds__(256) void supcon_kernel(const float* __restrict__ emb) {
    __shared__ float As[BK][BM + SPAD];
    __shared__ float Bs[BK][BN + SPAD];

    int rt = blockIdx.x;
    int b = blockIdx.y;
    const float* fb = emb + (size_t)b * HW * DIM;
    int tid = threadIdx.x;
    int tx = tid & 15;
    int ty = tid >> 4;
    int row0 = rt * BM;

    float dii[8], rl[8], S[8], P[8], C[8];
#pragma unroll
    for (int i = 0; i < 8; i++) {
        int r = row0 + ty * 8 + i;
        dii[i] = (r < HW) ? g_rn2[b * HW + r] : 0.f;
        rl[i] = (r < HW) ? (float)g_labels[b * HW + r] : -1.f;
        S[i] = P[i] = C[i] = 0.f;
    }

    for (int ct = 0; ct < CTILES; ct++) {
        int col0 = ct * BN;
        float acc[8][8];
#pragma unroll
        for (int i = 0; i < 8; i++)
#pragma unroll
            for (int j = 0; j < 8; j++) acc[i][j] = 0.f;

        for (int kt = 0; kt < DIM / BK; kt++) {
#pragma unroll
            for (int v = 0; v < 4; v++) {
                int idx = tid + 256 * v;      // 0..1023 float4 slots
                int r = idx >> 3;             // 0..127
                int k4 = idx & 7;             // 0..7
                float4 av = make_float4(0.f, 0.f, 0.f, 0.f);
                float4 bv = make_float4(0.f, 0.f, 0.f, 0.f);
                size_t koff = (size_t)kt * BK + k4 * 4;
                int ga = row0 + r, gc = col0 + r;
                if (ga < HW) av = *(const float4*)(fb + (size_t)ga * DIM + koff);
                if (gc < HW) bv = *(const float4*)(fb + (size_t)gc * DIM + koff);
                int k = k4 * 4;
                As[k + 0][r] = av.x; As[k + 1][r] = av.y;
                As[k + 2][r] = av.z; As[k + 3][r] = av.w;
                Bs[k + 0][r] = bv.x; Bs[k + 1][r] = bv.y;
                Bs[k + 2][r] = bv.z; Bs[k + 3][r] = bv.w;
            }
            __syncthreads();
#pragma unroll
            for (int k = 0; k < BK; k++) {
                float4 a0 = *(float4*)&As[k][ty * 8];
                float4 a1 = *(float4*)&As[k][ty * 8 + 4];
                float4 b0 = *(float4*)&Bs[k][tx * 8];
                float4 b1 = *(float4*)&Bs[k][tx * 8 + 4];
                float a[8] = {a0.x, a0.y, a0.z, a0.w, a1.x, a1.y, a1.z, a1.w};
                float bb[8] = {b0.x, b0.y, b0.z, b0.w, b1.x, b1.y, b1.z, b1.w};
#pragma unroll
                for (int i = 0; i < 8; i++)
#pragma unroll
                    for (int j = 0; j < 8; j++)
                        acc[i][j] = fmaf(a[i], bb[j], acc[i][j]);
            }
            __syncthreads();
        }

        // fused epilogue for this column tile
        float cl[8];
        int cok[8];
#pragma unroll
        for (int j = 0; j < 8; j++) {
            int c = col0 + tx * 8 + j;
            cok[j] = (c < HW);
            cl[j] = cok[j] ? (float)g_labels[b * HW + c] : -2.f;
        }
#pragma unroll
        for (int i = 0; i < 8; i++) {
            int r = row0 + ty * 8 + i;
            if (r >= HW) continue;
#pragma unroll
            for (int j = 0; j < 8; j++) {
                int c = col0 + tx * 8 + j;
                if (cok[j] && c != r) {
                    float x = (acc[i][j] - dii[i]) * INV_T;
                    S[i] += __expf(x);
                    if (cl[j] == rl[i]) { P[i] += x; C[i] += 1.f; }
                }
            }
        }
    }

    // reduce S,P,C across the 16 column-group lanes (shfl_xor stays in 16-lane group)
#pragma unroll
    for (int i = 0; i < 8; i++) {
#pragma unroll
        for (int o = 8; o >= 1; o >>= 1) {
            S[i] += __shfl_xor_sync(0xffffffffu, S[i], o);
            P[i] += __shfl_xor_sync(0xffffffffu, P[i], o);
            C[i] += __shfl_xor_sync(0xffffffffu, C[i], o);
        }
    }
    if (tx == 0) {
        float s = 0.f, n = 0.f;
#pragma unroll
        for (int i = 0; i < 8; i++) {
            int r = row0 + ty * 8 + i;
            if (r < HW && C[i] > 0.f) {
                s += -((P[i] - C[i] * logf(S[i] + 1e-6f)) / C[i]);
                n += 1.f;
            }
        }
        atomicAdd(&g_supcon_sum[b], s);
        atomicAdd(&g_anchor_cnt[b], n);
    }
}

// ---------------------------------------------------------------------------
// finalize: per-image supcon/separation/uniformity + cross-image aggregation
// ---------------------------------------------------------------------------
__global__ void finalize_kernel(const float* __restrict__ is_forged, float* __restrict__ out) {
    __shared__ float sc[BATCH], scv[BATCH], sp[BATCH], spv[BATCH], un[BATCH], unv[BATCH];
    int t = threadIdx.x;
    if (t < BATCH) {
        int b = t;
        // ---- supcon ----
        float na = g_anchor_cnt[b];
        float supcon = g_supcon_sum[b] / fmaxf(na, 1.f);
        float supcon_valid = (na > 0.f) ? 1.f : 0.f;

        // ---- centroids / separation ----
        float cnt[NLBL], cn[NLBL], inv[NLBL];
#pragma unroll
        for (int l = 0; l < NLBL; l++) {
            cnt[l] = g_cnt[b][l];
            inv[l] = 1.f / fmaxf(cnt[l], 1.f);
            float s = 0.f;
            for (int d = 0; d < DIM; d++) {
                float m = g_label_sums[b][l][d] * inv[l];
                s += m * m;
            }
            cn[l] = s;
        }
        float terms = 0.f;
        float npairs = 0.f;
        int npresent = 0;
#pragma unroll
        for (int l = 0; l < NLBL; l++) if (cnt[l] > 0.f) npresent++;
        for (int l1 = 0; l1 < NLBL; l1++) {
            for (int l2 = l1 + 1; l2 < NLBL; l2++) {
                if (cnt[l1] > 0.f && cnt[l2] > 0.f) {
                    float dot = 0.f;
                    for (int d = 0; d < DIM; d++)
                        dot += (g_label_sums[b][l1][d] * inv[l1]) *
                               (g_label_sums[b][l2][d] * inv[l2]);
                    float sq = cn[l1] + cn[l2] - 2.f * dot;
                    float dd = sqrtf(fmaxf(sq, 0.f));
                    terms += fmaxf(SEPM - dd, 0.f);
                    npairs += 1.f;
                }
            }
        }
        float sep = terms / fmaxf(npairs, 1.f);
        float sep_valid = (npresent >= 2) ? 1.f : 0.f;

        // ---- uniformity ----
        float uni, univ;
        if (is_forged[b] >= 0.5f) {
            float inst = 0.f, nl = 0.f;
#pragma unroll
            for (int l = 0; l < NLBL; l++) {
                float var = g_q[b][l] * inv[l] - cn[l];
                if (cnt[l] >= 2.f && var > UNITH) { inst += var - UNITH; nl += 1.f; }
            }
            uni = inst / fmaxf(nl, 1.f);
            univ = (nl > 0.f) ? 1.f : 0.f;
        } else {
            float qall = 0.f;
#pragma unroll
            for (int l = 0; l < NLBL; l++) qall += g_q[b][l];
            float nrm = 0.f;
            for (int d = 0; d < DIM; d++) {
                float s = 0.f;
#pragma unroll
                for (int l = 0; l < NLBL; l++) s += g_label_sums[b][l][d];
                s *= (1.f / (float)HW);
                nrm += s * s;
            }
            float var_all = qall * (1.f / (float)HW) - nrm;
            uni = (var_all > UNITH) ? (var_all - UNITH) : 0.f;
            univ = (var_all > UNITH) ? 1.f : 0.f;
        }

        sc[b] = supcon * supcon_valid; scv[b] = supcon_valid;
        sp[b] = sep * sep_valid;       spv[b] = sep_valid;
        un[b] = uni * univ;            unv[b] = univ;
    }
    __syncthreads();
    if (t == 0) {
        float a = 0.f, av = 0.f, s2 = 0.f, sv = 0.f, u = 0.f, uv = 0.f;
        for (int b = 0; b < BATCH; b++) {
            a += sc[b]; av += scv[b];
            s2 += sp[b]; sv += spv[b];
            u += un[b]; uv += unv[b];
        }
        float supcon = (av > 0.f) ? a / fmaxf(av, 1.f) : 0.f;
        float sep = (sv > 0.f) ? s2 / fmaxf(sv, 1.f) : 0.f;
        float uni = (uv > 0.f) ? u / fmaxf(uv, 1.f) : 0.f;
        out[0] = 1.0f * supcon + 0.5f * sep + 0.5f * uni;
    }
}

// ---------------------------------------------------------------------------
extern "C" void kernel_launch(void* const* d_in, const int* in_sizes, int n_in,
                              void* d_out, int out_size) {
    const float* emb   = (const float*)d_in[0];   // (16,33,33,512) f32
    const float* masks = (const float*)d_in[1];   // (16,6,33,33) f32
    const float* isf   = (const float*)d_in[2];   // (16,) f32
    float* out = (float*)d_out;

    prep_kernel<<<BATCH * NMASK + 1, 256>>>(masks);
    labels_kernel<<<(BATCH * HW + 255) / 256, 256>>>(masks);
    rn2_kernel<<<(BATCH * HW * 32 + 255) / 256, 256>>>(emb);
    centroid_kernel<<<BATCH, DIM>>>(emb);
    dim3 grid(CTILES, BATCH);
    supcon_kernel<<<grid, 256>>>(emb);
    finalize_kernel<<<1, 32>>>(isf, out);
}

// round 3
// speedup vs baseline: 1.0144x; 1.0144x over previous
#include <cuda_runtime.h>
#include <math.h>

#define BATCH 16
#define NMASK 6
#define HW 1089
#define DIM 512
#define NLBL 7
#define INV_T (1.0f/0.07f)
#define SEPM 2.0f
#define UNITH 0.1f

#define BM 128
#define BN 128
#define BK 32
#define SPAD 4
#define CTILES 9   // ceil(1089/128)

// ---- scratch (device globals: allocation-free) ----
__device__ float g_label_sums[BATCH][NLBL][DIM];
__device__ float g_cnt[BATCH][NLBL];
__device__ float g_q[BATCH][NLBL];
__device__ float g_supcon_sum[BATCH];
__device__ float g_anchor_cnt[BATCH];
__device__ int   g_active[BATCH * NMASK];
__device__ int   g_labels[BATCH * HW];
__device__ float g_rn2[BATCH * HW];

// ---------------------------------------------------------------------------
// prep: per-(b,m) mask channel sums -> active flags; zero atomic accumulators
// ---------------------------------------------------------------------------
__global__ void prep_kernel(const float* __restrict__ masks) {
    int blk = blockIdx.x;
    if (blk < BATCH * NMASK) {
        const float* m = masks + (size_t)blk * HW;
        float s = 0.f;
        for (int i = threadIdx.x; i < HW; i += blockDim.x) s += m[i];
        __shared__ float sh[256];
        sh[threadIdx.x] = s;
        __syncthreads();
        for (int o = 128; o > 0; o >>= 1) {
            if (threadIdx.x < o) sh[threadIdx.x] += sh[threadIdx.x + o];
            __syncthreads();
        }
        if (threadIdx.x == 0) g_active[blk] = (sh[0] > 0.f) ? 1 : 0;
    } else {
        if (threadIdx.x < BATCH) {
            g_supcon_sum[threadIdx.x] = 0.f;
            g_anchor_cnt[threadIdx.x] = 0.f;
        }
    }
}

// ---------------------------------------------------------------------------
// labels: per pixel, label = max over m of (m+1) where mask>0.5 & active
// ---------------------------------------------------------------------------
__global__ void labels_kernel(const float* __restrict__ masks) {
    int idx = blockIdx.x * blockDim.x + threadIdx.x;
    if (idx >= BATCH * HW) return;
    int b = idx / HW, n = idx - b * HW;
    const float* mb = masks + (size_t)b * NMASK * HW;
    int lbl = 0;
#pragma unroll
    for (int m = 0; m < NMASK; m++) {
        if (mb[(size_t)m * HW + n] > 0.5f && g_active[b * NMASK + m]) lbl = m + 1;
    }
    g_labels[idx] = lbl;
}

// ---------------------------------------------------------------------------
// rn2: per-pixel squared norm (one warp per pixel)
// ---------------------------------------------------------------------------
__global__ void rn2_kernel(const float* __restrict__ emb) {
    int w = (blockIdx.x * blockDim.x + threadIdx.x) >> 5;
    int lane = threadIdx.x & 31;
    if (w >= BATCH * HW) return;
    const float4* f = (const float4*)(emb + (size_t)w * DIM);
    float s = 0.f;
#pragma unroll
    for (int d4 = lane; d4 < DIM / 4; d4 += 32) {
        float4 v = f[d4];
        s += v.x * v.x + v.y * v.y + v.z * v.z + v.w * v.w;
    }
#pragma unroll
    for (int o = 16; o > 0; o >>= 1) s += __shfl_xor_sync(0xffffffffu, s, o);
    if (lane == 0) g_rn2[w] = s;
}

// ---------------------------------------------------------------------------
// centroids: per-image per-label feature sums, counts, sum of rn2
// one block per image, 512 threads (thread = dim)
// ---------------------------------------------------------------------------
__global__ void centroid_kernel(const float* __restrict__ emb) {
    int b = blockIdx.x;
    int t = threadIdx.x;
    const float* fb = emb + (size_t)b * HW * DIM;
    float acc[NLBL];
#pragma unroll
    for (int l = 0; l < NLBL; l++) acc[l] = 0.f;
    for (int n = 0; n < HW; n++) {
        int lbl = g_labels[b * HW + n];
        float v = fb[(size_t)n * DIM + t];
#pragma unroll
        for (int l = 0; l < NLBL; l++) acc[l] += (lbl == l) ? v : 0.f;
    }
#pragma unroll
    for (int l = 0; l < NLBL; l++) g_label_sums[b][l][t] = acc[l];
    if (t < NLBL) {
        float c = 0.f, q = 0.f;
        for (int n = 0; n < HW; n++) {
            if (g_labels[b * HW + n] == t) { c += 1.f; q += g_rn2[b * HW + n]; }
        }
        g_cnt[b][t] = c;
        g_q[b][t] = q;
    }
}

// ---------------------------------------------------------------------------
// supcon: fused Gram GEMM + streamed log-sum-exp epilogue.
// Block = 128 rows of one image. Loops over 9 column tiles of 128.
// Per row accumulate S (exp sum), P (positive logit sum), C (positive count).
// ---------------------------------------------------------------------------
__global__ __launch_bounds__(256) void supcon_kernel(const float* __restrict__ emb) {
    __shared__ float As[BK][BM + SPAD];
    __shared__ float Bs[BK][BN + SPAD];

    int rt = blockIdx.x;
    int b = blockIdx.y;
    const float* fb = emb + (size_t)b * HW * DIM;
    int tid = threadIdx.x;
    int tx = tid & 15;
    int ty = tid >> 4;
    int row0 = rt * BM;

    float dii[8], rl[8], S[8], P[8], C[8];
#pragma unroll
    for (int i = 0; i < 8; i++) {
        int r = row0 + ty * 8 + i;
        dii[i] = (r < HW) ? g_rn2[b * HW + r] : 0.f;
        rl[i] = (r < HW) ? (float)g_labels[b * HW + r] : -1.f;
        S[i] = P[i] = C[i] = 0.f;
    }

    for (int ct = 0; ct < CTILES; ct++) {
        int col0 = ct * BN;
        float acc[8][8];
#pragma unroll
        for (int i = 0; i < 8; i++)
#pragma unroll
            for (int j = 0; j < 8; j++) acc[i][j] = 0.f;

        for (int kt = 0; kt < DIM / BK; kt++) {
#pragma unroll
            for (int v = 0; v < 4; v++) {
                int idx = tid + 256 * v;      // 0..1023 float4 slots
                int r = idx >> 3;             // 0..127
                int k4 = idx & 7;             // 0..7
                float4 av = make_float4(0.f, 0.f, 0.f, 0.f);
                float4 bv = make_float4(0.f, 0.f, 0.f, 0.f);
                size_t koff = (size_t)kt * BK + k4 * 4;
                int ga = row0 + r, gc = col0 + r;
                if (ga < HW) av = *(const float4*)(fb + (size_t)ga * DIM + koff);
                if (gc < HW) bv = *(const float4*)(fb + (size_t)gc * DIM + koff);
                int k = k4 * 4;
                As[k + 0][r] = av.x; As[k + 1][r] = av.y;
                As[k + 2][r] = av.z; As[k + 3][r] = av.w;
                Bs[k + 0][r] = bv.x; Bs[k + 1][r] = bv.y;
                Bs[k + 2][r] = bv.z; Bs[k + 3][r] = bv.w;
            }
            __syncthreads();
#pragma unroll
            for (int k = 0; k < BK; k++) {
                float4 a0 = *(float4*)&As[k][ty * 8];
                float4 a1 = *(float4*)&As[k][ty * 8 + 4];
                float4 b0 = *(float4*)&Bs[k][tx * 8];
                float4 b1 = *(float4*)&Bs[k][tx * 8 + 4];
                float a[8] = {a0.x, a0.y, a0.z, a0.w, a1.x, a1.y, a1.z, a1.w};
                float bb[8] = {b0.x, b0.y, b0.z, b0.w, b1.x, b1.y, b1.z, b1.w};
#pragma unroll
                for (int i = 0; i < 8; i++)
#pragma unroll
                    for (int j = 0; j < 8; j++)
                        acc[i][j] = fmaf(a[i], bb[j], acc[i][j]);
            }
            __syncthreads();
        }

        // fused epilogue for this column tile
        float cl[8];
        int cok[8];
#pragma unroll
        for (int j = 0; j < 8; j++) {
            int c = col0 + tx * 8 + j;
            cok[j] = (c < HW);
            cl[j] = cok[j] ? (float)g_labels[b * HW + c] : -2.f;
        }
#pragma unroll
        for (int i = 0; i < 8; i++) {
            int r = row0 + ty * 8 + i;
            if (r >= HW) continue;
#pragma unroll
            for (int j = 0; j < 8; j++) {
                int c = col0 + tx * 8 + j;
                if (cok[j] && c != r) {
                    float x = (acc[i][j] - dii[i]) * INV_T;
                    S[i] += __expf(x);
                    if (cl[j] == rl[i]) { P[i] += x; C[i] += 1.f; }
                }
            }
        }
    }

    // reduce S,P,C across the 16 column-group lanes (shfl_xor stays in 16-lane group)
#pragma unroll
    for (int i = 0; i < 8; i++) {
#pragma unroll
        for (int o = 8; o >= 1; o >>= 1) {
            S[i] += __shfl_xor_sync(0xffffffffu, S[i], o);
            P[i] += __shfl_xor_sync(0xffffffffu, P[i], o);
            C[i] += __shfl_xor_sync(0xffffffffu, C[i], o);
        }
    }
    if (tx == 0) {
        float s = 0.f, n = 0.f;
#pragma unroll
        for (int i = 0; i < 8; i++) {
            int r = row0 + ty * 8 + i;
            if (r < HW && C[i] > 0.f) {
                s += -((P[i] - C[i] * logf(S[i] + 1e-6f)) / C[i]);
                n += 1.f;
            }
        }
        atomicAdd(&g_supcon_sum[b], s);
        atomicAdd(&g_anchor_cnt[b], n);
    }
}

// ---------------------------------------------------------------------------
// finalize: per-image supcon/separation/uniformity + cross-image aggregation
// ---------------------------------------------------------------------------
__global__ void finalize_kernel(const float* __restrict__ is_forged, float* __restrict__ out) {
    __shared__ float sc[BATCH], scv[BATCH], sp[BATCH], spv[BATCH], un[BATCH], unv[BATCH];
    int t = threadIdx.x;
    if (t < BATCH) {
        int b = t;
        // ---- supcon ----
        float na = g_anchor_cnt[b];
        float supcon = g_supcon_sum[b] / fmaxf(na, 1.f);
        float supcon_valid = (na > 0.f) ? 1.f : 0.f;

        // ---- centroids / separation ----
        float cnt[NLBL], cn[NLBL], inv[NLBL];
#pragma unroll
        for (int l = 0; l < NLBL; l++) {
            cnt[l] = g_cnt[b][l];
            inv[l] = 1.f / fmaxf(cnt[l], 1.f);
            float s = 0.f;
            for (int d = 0; d < DIM; d++) {
                float m = g_label_sums[b][l][d] * inv[l];
                s += m * m;
            }
            cn[l] = s;
        }
        float terms = 0.f;
        float npairs = 0.f;
        int npresent = 0;
#pragma unroll
        for (int l = 0; l < NLBL; l++) if (cnt[l] > 0.f) npresent++;
        for (int l1 = 0; l1 < NLBL; l1++) {
            for (int l2 = l1 + 1; l2 < NLBL; l2++) {
                if (cnt[l1] > 0.f && cnt[l2] > 0.f) {
                    float dot = 0.f;
                    for (int d = 0; d < DIM; d++)
                        dot += (g_label_sums[b][l1][d] * inv[l1]) *
                               (g_label_sums[b][l2][d] * inv[l2]);
                    float sq = cn[l1] + cn[l2] - 2.f * dot;
                    float dd = sqrtf(fmaxf(sq, 0.f));
                    terms += fmaxf(SEPM - dd, 0.f);
                    npairs += 1.f;
                }
            }
        }
        float sep = terms / fmaxf(npairs, 1.f);
        float sep_valid = (npresent >= 2) ? 1.f : 0.f;

        // ---- uniformity ----
        float uni, univ;
        if (is_forged[b] >= 0.5f) {
            float inst = 0.f, nl = 0.f;
#pragma unroll
            for (int l = 0; l < NLBL; l++) {
                float var = g_q[b][l] * inv[l] - cn[l];
                if (cnt[l] >= 2.f && var > UNITH) { inst += var - UNITH; nl += 1.f; }
            }
            uni = inst / fmaxf(nl, 1.f);
            univ = (nl > 0.f) ? 1.f : 0.f;
        } else {
            float qall = 0.f;
#pragma unroll
            for (int l = 0; l < NLBL; l++) qall += g_q[b][l];
            float nrm = 0.f;
            for (int d = 0; d < DIM; d++) {
                float s = 0.f;
#pragma unroll
                for (int l = 0; l < NLBL; l++) s += g_label_sums[b][l][d];
                s *= (1.f / (float)HW);
                nrm += s * s;
            }
            float var_all = qall * (1.f / (float)HW) - nrm;
            uni = (var_all > UNITH) ? (var_all - UNITH) : 0.f;
            univ = (var_all > UNITH) ? 1.f : 0.f;
        }

        sc[b] = supcon * supcon_valid; scv[b] = supcon_valid;
        sp[b] = sep * sep_valid;       spv[b] = sep_valid;
        un[b] = uni * univ;            unv[b] = univ;
    }
    __syncthreads();
    if (t == 0) {
        float a = 0.f, av = 0.f, s2 = 0.f, sv = 0.f, u = 0.f, uv = 0.f;
        for (int b = 0; b < BATCH; b++) {
            a += sc[b]; av += scv[b];
            s2 += sp[b]; sv += spv[b];
            u += un[b]; uv += unv[b];
        }
        float supcon = (av > 0.f) ? a / fmaxf(av, 1.f) : 0.f;
        float sep = (sv > 0.f) ? s2 / fmaxf(sv, 1.f) : 0.f;
        float uni = (uv > 0.f) ? u / fmaxf(uv, 1.f) : 0.f;
        out[0] = 1.0f * supcon + 0.5f * sep + 0.5f * uni;
    }
}

// ---------------------------------------------------------------------------
extern "C" void kernel_launch(void* const* d_in, const int* in_sizes, int n_in,
                              void* d_out, int out_size) {
    const float* emb   = (const float*)d_in[0];   // (16,33,33,512) f32
    const float* masks = (const float*)d_in[1];   // (16,6,33,33) f32
    const float* isf   = (const float*)d_in[2];   // (16,) f32
    float* out = (float*)d_out;

    prep_kernel<<<BATCH * NMASK + 1, 256>>>(masks);
    labels_kernel<<<(BATCH * HW + 255) / 256, 256>>>(masks);
    rn2_kernel<<<(BATCH * HW * 32 + 255) / 256, 256>>>(emb);
    centroid_kernel<<<BATCH, DIM>>>(emb);
    dim3 grid(CTILES, BATCH);
    supcon_kernel<<<grid, 256>>>(emb);
    finalize_kernel<<<1, 32>>>(isf, out);
}

// round 4
// speedup vs baseline: 1.4023x; 1.3823x over previous
#include <cuda_runtime.h>
#include <math.h>

#define BATCH 16
#define NMASK 6
#define HW 1089
#define DIM 512
#define NLBL 7
#define INV_T (1.0f/0.07f)
#define SEPM 2.0f
#define UNITH 0.1f

#define BM 128
#define BN 128
#define BK 32
#define SPAD 4
#define CTILES 9          // ceil(1089/128)
#define NTILEPAIRS 45     // CTILES*(CTILES+1)/2
#define CCH 9             // centroid chunks (121 rows each)

// ---- scratch (device globals: allocation-free) ----
__device__ float g_label_sums[BATCH][NLBL][DIM];
__device__ float g_cnt[BATCH][NLBL];
__device__ float g_q[BATCH][NLBL];
__device__ float g_supcon_sum[BATCH];
__device__ float g_anchor_cnt[BATCH];
__device__ int   g_active[BATCH * NMASK];
__device__ int   g_labels[BATCH * HW];
__device__ float g_rn2[BATCH * HW];
__device__ float g_S[BATCH * HW];
__device__ float g_P[BATCH * HW];
__device__ float g_C[BATCH * HW];

// ---------------------------------------------------------------------------
// zero: clear all atomic accumulators
// ---------------------------------------------------------------------------
__global__ void zero_kernel() {
    int i = blockIdx.x * blockDim.x + threadIdx.x;
    if (i < BATCH * NLBL * DIM) ((float*)g_label_sums)[i] = 0.f;
    if (i < BATCH * NLBL) { ((float*)g_cnt)[i] = 0.f; ((float*)g_q)[i] = 0.f; }
    if (i < BATCH * HW) { g_S[i] = 0.f; g_P[i] = 0.f; g_C[i] = 0.f; }
}

// ---------------------------------------------------------------------------
// prep: per-(b,m) mask channel sums -> active flags
// ---------------------------------------------------------------------------
__global__ void prep_kernel(const float* __restrict__ masks) {
    int blk = blockIdx.x;
    const float* m = masks + (size_t)blk * HW;
    float s = 0.f;
    for (int i = threadIdx.x; i < HW; i += blockDim.x) s += m[i];
    __shared__ float sh[256];
    sh[threadIdx.x] = s;
    __syncthreads();
    for (int o = 128; o > 0; o >>= 1) {
        if (threadIdx.x < o) sh[threadIdx.x] += sh[threadIdx.x + o];
        __syncthreads();
    }
    if (threadIdx.x == 0) g_active[blk] = (sh[0] > 0.f) ? 1 : 0;
}

// ---------------------------------------------------------------------------
// labels: per pixel, label = max over m of (m+1) where mask>0.5 & active
// ---------------------------------------------------------------------------
__global__ void labels_kernel(const float* __restrict__ masks) {
    int idx = blockIdx.x * blockDim.x + threadIdx.x;
    if (idx >= BATCH * HW) return;
    int b = idx / HW, n = idx - b * HW;
    const float* mb = masks + (size_t)b * NMASK * HW;
    int lbl = 0;
#pragma unroll
    for (int m = 0; m < NMASK; m++) {
        if (mb[(size_t)m * HW + n] > 0.5f && g_active[b * NMASK + m]) lbl = m + 1;
    }
    g_labels[idx] = lbl;
}

// ---------------------------------------------------------------------------
// rn2: per-pixel squared norm (one warp per pixel)
// ---------------------------------------------------------------------------
__global__ void rn2_kernel(const float* __restrict__ emb) {
    int w = (blockIdx.x * blockDim.x + threadIdx.x) >> 5;
    int lane = threadIdx.x & 31;
    if (w >= BATCH * HW) return;
    const float4* f = (const float4*)(emb + (size_t)w * DIM);
    float s = 0.f;
#pragma unroll
    for (int d4 = lane; d4 < DIM / 4; d4 += 32) {
        float4 v = f[d4];
        s += v.x * v.x + v.y * v.y + v.z * v.z + v.w * v.w;
    }
#pragma unroll
    for (int o = 16; o > 0; o >>= 1) s += __shfl_xor_sync(0xffffffffu, s, o);
    if (lane == 0) g_rn2[w] = s;
}

// ---------------------------------------------------------------------------
// centroids: parallel over (chunk, image). Each block sums 121 rows.
// ---------------------------------------------------------------------------
__global__ void centroid_kernel(const float* __restrict__ emb) {
    int chunk = blockIdx.x;
    int b = blockIdx.y;
    int t = threadIdx.x;
    int r0 = chunk * 121, r1 = r0 + 121;
    const float* fb = emb + (size_t)b * HW * DIM;
    float acc[NLBL];
#pragma unroll
    for (int l = 0; l < NLBL; l++) acc[l] = 0.f;
    for (int n = r0; n < r1; n++) {
        int lbl = g_labels[b * HW + n];
        float v = fb[(size_t)n * DIM + t];
#pragma unroll
        for (int l = 0; l < NLBL; l++) acc[l] += (lbl == l) ? v : 0.f;
    }
#pragma unroll
    for (int l = 0; l < NLBL; l++)
        if (acc[l] != 0.f) atomicAdd(&g_label_sums[b][l][t], acc[l]);
    if (t < NLBL) {
        float c = 0.f, q = 0.f;
        for (int n = r0; n < r1; n++) {
            if (g_labels[b * HW + n] == t) { c += 1.f; q += g_rn2[b * HW + n]; }
        }
        if (c != 0.f) { atomicAdd(&g_cnt[b][t], c); atomicAdd(&g_q[b][t], q); }
    }
}

// ---------------------------------------------------------------------------
// supcon tiles: symmetric — only tiles ct >= rt. Each block computes one
// 128x128 Gram tile (K=512) and scatters exp/logit contributions to row
// accumulators, and for off-diagonal tiles also to column accumulators.
// Row-max subtraction uses the constant 1.0 (= ||e||^2 for unit vectors);
// exact shift-invariance of log_prob makes this equivalent to the reference.
// ---------------------------------------------------------------------------
__global__ __launch_bounds__(256, 1) void supcon_tile_kernel(const float* __restrict__ emb) {
    __shared__ float As[BK][BM + SPAD];
    __shared__ float Bs[BK][BN + SPAD];
    __shared__ float colS[BN], colP[BN], colC[BN];

    int b = blockIdx.y;
    // map blockIdx.x -> (rt, ct) with ct >= rt
    int idx = blockIdx.x, rt = 0;
    while (idx >= CTILES - rt) { idx -= CTILES - rt; rt++; }
    int ct = rt + idx;
    bool diag = (ct == rt);

    const float* fb = emb + (size_t)b * HW * DIM;
    int tid = threadIdx.x;
    int tx = tid & 15;
    int ty = tid >> 4;
    int row0 = rt * BM;
    int col0 = ct * BN;

    if (tid < BN) { colS[tid] = 0.f; colP[tid] = 0.f; colC[tid] = 0.f; }

    float acc[8][8];
#pragma unroll
    for (int i = 0; i < 8; i++)
#pragma unroll
        for (int j = 0; j < 8; j++) acc[i][j] = 0.f;

    for (int kt = 0; kt < DIM / BK; kt++) {
#pragma unroll
        for (int v = 0; v < 4; v++) {
            int idx4 = tid + 256 * v;     // 0..1023 float4 slots
            int r = idx4 >> 3;            // 0..127
            int k4 = idx4 & 7;            // 0..7
            float4 av = make_float4(0.f, 0.f, 0.f, 0.f);
            float4 bv = make_float4(0.f, 0.f, 0.f, 0.f);
            size_t koff = (size_t)kt * BK + k4 * 4;
            int ga = row0 + r, gc = col0 + r;
            if (ga < HW) av = *(const float4*)(fb + (size_t)ga * DIM + koff);
            if (gc < HW) bv = *(const float4*)(fb + (size_t)gc * DIM + koff);
            int k = k4 * 4;
            As[k + 0][r] = av.x; As[k + 1][r] = av.y;
            As[k + 2][r] = av.z; As[k + 3][r] = av.w;
            Bs[k + 0][r] = bv.x; Bs[k + 1][r] = bv.y;
            Bs[k + 2][r] = bv.z; Bs[k + 3][r] = bv.w;
        }
        __syncthreads();
#pragma unroll
        for (int k = 0; k < BK; k++) {
            float4 a0 = *(float4*)&As[k][ty * 8];
            float4 a1 = *(float4*)&As[k][ty * 8 + 4];
            float4 b0 = *(float4*)&Bs[k][tx * 8];
            float4 b1 = *(float4*)&Bs[k][tx * 8 + 4];
            float a[8] = {a0.x, a0.y, a0.z, a0.w, a1.x, a1.y, a1.z, a1.w};
            float bb[8] = {b0.x, b0.y, b0.z, b0.w, b1.x, b1.y, b1.z, b1.w};
#pragma unroll
            for (int i = 0; i < 8; i++)
#pragma unroll
                for (int j = 0; j < 8; j++)
                    acc[i][j] = fmaf(a[i], bb[j], acc[i][j]);
        }
        __syncthreads();
    }

    // ---- fused epilogue ----
    float rl[8], cl[8];
    int cok[8];
#pragma unroll
    for (int i = 0; i < 8; i++) {
        int r = row0 + ty * 8 + i;
        rl[i] = (r < HW) ? (float)g_labels[b * HW + r] : -1.f;
    }
#pragma unroll
    for (int j = 0; j < 8; j++) {
        int c = col0 + tx * 8 + j;
        cok[j] = (c < HW);
        cl[j] = cok[j] ? (float)g_labels[b * HW + c] : -2.f;
    }

    float S[8], P[8], C[8], Sc[8], Pc[8], Cc[8];
#pragma unroll
    for (int i = 0; i < 8; i++) { S[i] = P[i] = C[i] = 0.f; Sc[i] = Pc[i] = Cc[i] = 0.f; }

#pragma unroll
    for (int i = 0; i < 8; i++) {
        int r = row0 + ty * 8 + i;
        if (r >= HW) continue;
#pragma unroll
        for (int j = 0; j < 8; j++) {
            int c = col0 + tx * 8 + j;
            if (cok[j] && c != r) {
                float x = (acc[i][j] - 1.0f) * INV_T;
                float e = __expf(x);
                bool same = (cl[j] == rl[i]);
                S[i] += e;
                if (same) { P[i] += x; C[i] += 1.f; }
                if (!diag) {
                    Sc[j] += e;
                    if (same) { Pc[j] += x; Cc[j] += 1.f; }
                }
            }
        }
    }

    // ---- row reduction across the 16 tx lanes (stays inside 16-lane halves) ----
#pragma unroll
    for (int i = 0; i < 8; i++) {
#pragma unroll
        for (int o = 8; o >= 1; o >>= 1) {
            S[i] += __shfl_xor_sync(0xffffffffu, S[i], o);
            P[i] += __shfl_xor_sync(0xffffffffu, P[i], o);
            C[i] += __shfl_xor_sync(0xffffffffu, C[i], o);
        }
    }
    if (tx == 0) {
#pragma unroll
        for (int i = 0; i < 8; i++) {
            int r = row0 + ty * 8 + i;
            if (r < HW) {
                atomicAdd(&g_S[b * HW + r], S[i]);
                atomicAdd(&g_P[b * HW + r], P[i]);
                atomicAdd(&g_C[b * HW + r], C[i]);
            }
        }
    }

    // ---- column reduction (off-diagonal tiles only) ----
    if (!diag) {
        // combine the two ty values inside each warp (lanes 0-15 <-> 16-31)
#pragma unroll
        for (int j = 0; j < 8; j++) {
            Sc[j] += __shfl_xor_sync(0xffffffffu, Sc[j], 16);
            Pc[j] += __shfl_xor_sync(0xffffffffu, Pc[j], 16);
            Cc[j] += __shfl_xor_sync(0xffffffffu, Cc[j], 16);
        }
        if ((tid & 31) < 16) {
#pragma unroll
            for (int j = 0; j < 8; j++) {
                int cc = tx * 8 + j;
                atomicAdd(&colS[cc], Sc[j]);
                atomicAdd(&colP[cc], Pc[j]);
                atomicAdd(&colC[cc], Cc[j]);
            }
        }
        __syncthreads();
        if (tid < BN) {
            int c = col0 + tid;
            if (c < HW) {
                atomicAdd(&g_S[b * HW + c], colS[tid]);
                atomicAdd(&g_P[b * HW + c], colP[tid]);
                atomicAdd(&g_C[b * HW + c], colC[tid]);
            }
        }
    }
}

// ---------------------------------------------------------------------------
// per-row supcon loss + per-image reduction (one block per image)
// ---------------------------------------------------------------------------
__global__ void supcon_row_kernel() {
    int b = blockIdx.x;
    int t = threadIdx.x;
    float s = 0.f, n = 0.f;
    for (int r = t; r < HW; r += 256) {
        float c = g_C[b * HW + r];
        if (c > 0.f) {
            s += -((g_P[b * HW + r] - c * logf(g_S[b * HW + r] + 1e-6f)) / c);
            n += 1.f;
        }
    }
    __shared__ float sS[256], sN[256];
    sS[t] = s; sN[t] = n;
    __syncthreads();
    for (int o = 128; o > 0; o >>= 1) {
        if (t < o) { sS[t] += sS[t + o]; sN[t] += sN[t + o]; }
        __syncthreads();
    }
    if (t == 0) { g_supcon_sum[b] = sS[0]; g_anchor_cnt[b] = sN[0]; }
}

// ---------------------------------------------------------------------------
// finalize: per-image supcon/separation/uniformity + cross-image aggregation
// ---------------------------------------------------------------------------
__global__ void finalize_kernel(const float* __restrict__ is_forged, float* __restrict__ out) {
    __shared__ float sc[BATCH], scv[BATCH], sp[BATCH], spv[BATCH], un[BATCH], unv[BATCH];
    int t = threadIdx.x;
    if (t < BATCH) {
        int b = t;
        float na = g_anchor_cnt[b];
        float supcon = g_supcon_sum[b] / fmaxf(na, 1.f);
        float supcon_valid = (na > 0.f) ? 1.f : 0.f;

        float cnt[NLBL], cn[NLBL], inv[NLBL];
#pragma unroll
        for (int l = 0; l < NLBL; l++) {
            cnt[l] = g_cnt[b][l];
            inv[l] = 1.f / fmaxf(cnt[l], 1.f);
            float s = 0.f;
            for (int d = 0; d < DIM; d++) {
                float m = g_label_sums[b][l][d] * inv[l];
                s += m * m;
            }
            cn[l] = s;
        }
        float terms = 0.f, npairs = 0.f;
        int npresent = 0;
#pragma unroll
        for (int l = 0; l < NLBL; l++) if (cnt[l] > 0.f) npresent++;
        for (int l1 = 0; l1 < NLBL; l1++) {
            for (int l2 = l1 + 1; l2 < NLBL; l2++) {
                if (cnt[l1] > 0.f && cnt[l2] > 0.f) {
                    float dot = 0.f;
                    for (int d = 0; d < DIM; d++)
                        dot += (g_label_sums[b][l1][d] * inv[l1]) *
                               (g_label_sums[b][l2][d] * inv[l2]);
                    float sq = cn[l1] + cn[l2] - 2.f * dot;
                    float dd = sqrtf(fmaxf(sq, 0.f));
                    terms += fmaxf(SEPM - dd, 0.f);
                    npairs += 1.f;
                }
            }
        }
        float sep = terms / fmaxf(npairs, 1.f);
        float sep_valid = (npresent >= 2) ? 1.f : 0.f;

        float uni, univ;
        if (is_forged[b] >= 0.5f) {
            float inst = 0.f, nl = 0.f;
#pragma unroll
            for (int l = 0; l < NLBL; l++) {
                float var = g_q[b][l] * inv[l] - cn[l];
                if (cnt[l] >= 2.f && var > UNITH) { inst += var - UNITH; nl += 1.f; }
            }
            uni = inst / fmaxf(nl, 1.f);
            univ = (nl > 0.f) ? 1.f : 0.f;
        } else {
            float qall = 0.f;
#pragma unroll
            for (int l = 0; l < NLBL; l++) qall += g_q[b][l];
            float nrm = 0.f;
            for (int d = 0; d < DIM; d++) {
                float s = 0.f;
#pragma unroll
                for (int l = 0; l < NLBL; l++) s += g_label_sums[b][l][d];
                s *= (1.f / (float)HW);
                nrm += s * s;
            }
            float var_all = qall * (1.f / (float)HW) - nrm;
            uni = (var_all > UNITH) ? (var_all - UNITH) : 0.f;
            univ = (var_all > UNITH) ? 1.f : 0.f;
        }

        sc[b] = supcon * supcon_valid; scv[b] = supcon_valid;
        sp[b] = sep * sep_valid;       spv[b] = sep_valid;
        un[b] = uni * univ;            unv[b] = univ;
    }
    __syncthreads();
    if (t == 0) {
        float a = 0.f, av = 0.f, s2 = 0.f, sv = 0.f, u = 0.f, uv = 0.f;
        for (int b = 0; b < BATCH; b++) {
            a += sc[b]; av += scv[b];
            s2 += sp[b]; sv += spv[b];
            u += un[b]; uv += unv[b];
        }
        float supcon = (av > 0.f) ? a / fmaxf(av, 1.f) : 0.f;
        float sep = (sv > 0.f) ? s2 / fmaxf(sv, 1.f) : 0.f;
        float uni = (uv > 0.f) ? u / fmaxf(uv, 1.f) : 0.f;
        out[0] = 1.0f * supcon + 0.5f * sep + 0.5f * uni;
    }
}

// ---------------------------------------------------------------------------
extern "C" void kernel_launch(void* const* d_in, const int* in_sizes, int n_in,
                              void* d_out, int out_size) {
    const float* emb   = (const float*)d_in[0];   // (16,33,33,512) f32
    const float* masks = (const float*)d_in[1];   // (16,6,33,33) f32
    const float* isf   = (const float*)d_in[2];   // (16,) f32
    float* out = (float*)d_out;

    zero_kernel<<<(BATCH * NLBL * DIM + 255) / 256, 256>>>();
    prep_kernel<<<BATCH * NMASK, 256>>>(masks);
    labels_kernel<<<(BATCH * HW + 255) / 256, 256>>>(masks);
    rn2_kernel<<<(BATCH * HW * 32 + 255) / 256, 256>>>(emb);
    centroid_kernel<<<dim3(CCH, BATCH), DIM>>>(emb);
    supcon_tile_kernel<<<dim3(NTILEPAIRS, BATCH), 256>>>(emb);
    supcon_row_kernel<<<BATCH, 256>>>();
    finalize_kernel<<<1, 32>>>(isf, out);
}

// round 6
// speedup vs baseline: 1.8095x; 1.2904x over previous
#include <cuda_runtime.h>
#include <cuda_bf16.h>
#include <cstdint>
#include <math.h>

#define BATCH 16
#define NMASK 6
#define HW 1089
#define DIM 512
#define NLBL 7
#define INV_T (1.0f/0.07f)
#define SEPM 2.0f
#define UNITH 0.1f

#define CTILES 9          // ceil(1089/128)
#define NTILEPAIRS 45     // CTILES*(CTILES+1)/2
#define CCH 33            // centroid chunks (33 rows each)

// ---- smem layout for supcon_mma (dynamic) ----
#define SM_LROW 0
#define SM_LCOL 512
#define SM_ROWS 1024
#define SM_ROWP 1536
#define SM_ROWC 2048
#define SM_BUF  2560
#define MATSZ   16384                 // 128 rows x 64 bf16 (128B/row)
#define STAGESZ (4*MATSZ)             // Ahi,Alo,Bhi,Blo
#define SM_E    2560                  // aliases buffers (post-MMA)
#define SM_X    (2560 + 128*132*4)
#define SM_TOTAL (2560 + 2*128*132*4) // 137728

// ---- scratch (device globals: allocation-free) ----
__device__ float g_label_sums[BATCH][NLBL][DIM];
__device__ float g_cnt[BATCH][NLBL];
__device__ float g_q[BATCH][NLBL];
__device__ float g_supcon_sum[BATCH];
__device__ float g_anchor_cnt[BATCH];
__device__ int   g_active[BATCH * NMASK];
__device__ int   g_labels[BATCH * HW];
__device__ float g_rn2[BATCH * HW];
__device__ float g_S[BATCH * HW];
__device__ float g_P[BATCH * HW];
__device__ float g_C[BATCH * HW];
__device__ __align__(16) __nv_bfloat16 g_hi[(size_t)BATCH * HW * DIM];
__device__ __align__(16) __nv_bfloat16 g_lo[(size_t)BATCH * HW * DIM];

// ================= helpers =================
__device__ __forceinline__ uint32_t smem_u32(const void* p) {
    uint32_t a;
    asm("{ .reg .u64 t; cvta.to.shared.u64 t, %1; cvt.u32.u64 %0, t; }" : "=r"(a) : "l"(p));
    return a;
}
__device__ __forceinline__ void ldsm4(uint32_t* r, uint32_t addr) {
    asm volatile("ldmatrix.sync.aligned.m8n8.x4.shared.b16 {%0,%1,%2,%3}, [%4];"
                 : "=r"(r[0]), "=r"(r[1]), "=r"(r[2]), "=r"(r[3]) : "r"(addr));
}
__device__ __forceinline__ void mma_bf16(float* c, const uint32_t* a, const uint32_t* b) {
    asm volatile("mma.sync.aligned.m16n8k16.row.col.f32.bf16.bf16.f32 "
                 "{%0,%1,%2,%3}, {%4,%5,%6,%7}, {%8,%9}, {%0,%1,%2,%3};"
                 : "+f"(c[0]), "+f"(c[1]), "+f"(c[2]), "+f"(c[3])
                 : "r"(a[0]), "r"(a[1]), "r"(a[2]), "r"(a[3]), "r"(b[0]), "r"(b[1]));
}

// ---------------------------------------------------------------------------
// zero: clear all atomic accumulators
// ---------------------------------------------------------------------------
__global__ void zero_kernel() {
    int i = blockIdx.x * blockDim.x + threadIdx.x;
    if (i < BATCH * NLBL * DIM) ((float*)g_label_sums)[i] = 0.f;
    if (i < BATCH * NLBL) { ((float*)g_cnt)[i] = 0.f; ((float*)g_q)[i] = 0.f; }
    if (i < BATCH * HW) { g_S[i] = 0.f; g_P[i] = 0.f; g_C[i] = 0.f; }
}

// ---------------------------------------------------------------------------
// prep: per-(b,m) mask channel sums -> active flags
// ---------------------------------------------------------------------------
__global__ void prep_kernel(const float* __restrict__ masks) {
    int blk = blockIdx.x;
    const float* m = masks + (size_t)blk * HW;
    float s = 0.f;
    for (int i = threadIdx.x; i < HW; i += blockDim.x) s += m[i];
    __shared__ float sh[256];
    sh[threadIdx.x] = s;
    __syncthreads();
    for (int o = 128; o > 0; o >>= 1) {
        if (threadIdx.x < o) sh[threadIdx.x] += sh[threadIdx.x + o];
        __syncthreads();
    }
    if (threadIdx.x == 0) g_active[blk] = (sh[0] > 0.f) ? 1 : 0;
}

// ---------------------------------------------------------------------------
// labels
// ---------------------------------------------------------------------------
__global__ void labels_kernel(const float* __restrict__ masks) {
    int idx = blockIdx.x * blockDim.x + threadIdx.x;
    if (idx >= BATCH * HW) return;
    int b = idx / HW, n = idx - b * HW;
    const float* mb = masks + (size_t)b * NMASK * HW;
    int lbl = 0;
#pragma unroll
    for (int m = 0; m < NMASK; m++) {
        if (mb[(size_t)m * HW + n] > 0.5f && g_active[b * NMASK + m]) lbl = m + 1;
    }
    g_labels[idx] = lbl;
}

// ---------------------------------------------------------------------------
// rn2 + fp32 -> bf16 (hi,lo) split conversion. One warp per pixel.
// ---------------------------------------------------------------------------
__global__ void rn2_cvt_kernel(const float* __restrict__ emb) {
    int w = (blockIdx.x * blockDim.x + threadIdx.x) >> 5;
    int lane = threadIdx.x & 31;
    if (w >= BATCH * HW) return;
    const float4* src = (const float4*)(emb + (size_t)w * DIM) + lane * 4;
    __nv_bfloat16 hh[16], ll[16];
    float s = 0.f;
#pragma unroll
    for (int k = 0; k < 4; k++) {
        float4 v = src[k];
        float vv[4] = {v.x, v.y, v.z, v.w};
#pragma unroll
        for (int e = 0; e < 4; e++) {
            float f = vv[e];
            s += f * f;
            __nv_bfloat16 h = __float2bfloat16(f);
            hh[k * 4 + e] = h;
            ll[k * 4 + e] = __float2bfloat16(f - __bfloat162float(h));
        }
    }
#pragma unroll
    for (int o = 16; o > 0; o >>= 1) s += __shfl_xor_sync(0xffffffffu, s, o);
    if (lane == 0) g_rn2[w] = s;
    uint4* dh = (uint4*)(g_hi + (size_t)w * DIM + lane * 16);
    uint4* dl = (uint4*)(g_lo + (size_t)w * DIM + lane * 16);
    dh[0] = ((uint4*)hh)[0]; dh[1] = ((uint4*)hh)[1];
    dl[0] = ((uint4*)ll)[0]; dl[1] = ((uint4*)ll)[1];
}

// ---------------------------------------------------------------------------
// centroids: parallel over (chunk, image). Each block sums 33 rows.
// ---------------------------------------------------------------------------
__global__ void centroid_kernel(const float* __restrict__ emb) {
    int chunk = blockIdx.x;
    int b = blockIdx.y;
    int t = threadIdx.x;
    int r0 = chunk * 33, r1 = r0 + 33;
    const float* fb = emb + (size_t)b * HW * DIM;
    float acc[NLBL];
#pragma unroll
    for (int l = 0; l < NLBL; l++) acc[l] = 0.f;
    for (int n = r0; n < r1; n++) {
        int lbl = g_labels[b * HW + n];
        float v = fb[(size_t)n * DIM + t];
#pragma unroll
        for (int l = 0; l < NLBL; l++) acc[l] += (lbl == l) ? v : 0.f;
    }
#pragma unroll
    for (int l = 0; l < NLBL; l++)
        if (acc[l] != 0.f) atomicAdd(&g_label_sums[b][l][t], acc[l]);
    if (t < NLBL) {
        float c = 0.f, q = 0.f;
        for (int n = r0; n < r1; n++) {
            if (g_labels[b * HW + n] == t) { c += 1.f; q += g_rn2[b * HW + n]; }
        }
        if (c != 0.f) { atomicAdd(&g_cnt[b][t], c); atomicAdd(&g_q[b][t], q); }
    }
}

// ---------------------------------------------------------------------------
// supcon Gram tile via mma.sync bf16 split-precision (hi*hi + hi*lo + lo*hi).
// One 128x128 tile per block (symmetric: only ct>=rt), K=512 in 8 chunks of
// 64, double-buffered cp.async, ldmatrix fragments, fused exp epilogue with
// symmetric row+column scatter.
// ---------------------------------------------------------------------------
__global__ __launch_bounds__(256, 1) void supcon_mma_kernel() {
    extern __shared__ char smem[];
    uint32_t sb = smem_u32(smem);
    int tid = threadIdx.x;
    int wid = tid >> 5, lane = tid & 31;
    int wr = wid >> 1, wc = wid & 1;
    int b = blockIdx.y;
    int idx = blockIdx.x, rt = 0;
    while (idx >= CTILES - rt) { idx -= CTILES - rt; rt++; }
    int ct = rt + idx;
    bool diag = (ct == rt);
    int row0 = rt * 128, col0 = ct * 128;

    int* lrow = (int*)(smem + SM_LROW);
    int* lcol = (int*)(smem + SM_LCOL);
    float* rowS = (float*)(smem + SM_ROWS);
    float* rowP = (float*)(smem + SM_ROWP);
    float* rowC = (float*)(smem + SM_ROWC);
    if (tid < 128) {
        int r = row0 + tid, c = col0 + tid;
        lrow[tid] = (r < HW) ? g_labels[b * HW + r] : -1;
        lcol[tid] = (c < HW) ? g_labels[b * HW + c] : -2;
        rowS[tid] = 0.f; rowP[tid] = 0.f; rowC[tid] = 0.f;
    }

    const __nv_bfloat16* bhp = g_hi + (size_t)b * HW * DIM;
    const __nv_bfloat16* blp = g_lo + (size_t)b * HW * DIM;

    // ---- cp.async stage loader: 4 mats x 16KB, SW128 xor swizzle ----
    auto load_stage = [&](int c, int p) {
        uint32_t dst_base = sb + SM_BUF + p * STAGESZ;
#pragma unroll
        for (int it = 0; it < 16; it++) {
            int mat = it >> 2;
            int idxm = tid + 256 * (it & 3);
            int row = idxm >> 3, seg = idxm & 7;
            int grow = ((mat < 2) ? row0 : col0) + row;
            uint32_t sz = (grow < HW) ? 16u : 0u;
            int gcl = (grow < HW) ? grow : 0;
            const __nv_bfloat16* srcb = (mat & 1) ? blp : bhp;
            const __nv_bfloat16* src = srcb + (size_t)gcl * DIM + c * 64 + seg * 8;
            uint32_t dst = dst_base + mat * MATSZ + row * 128 +
                           (((uint32_t)(seg * 16)) ^ (((uint32_t)row & 7u) << 4));
            asm volatile("cp.async.cg.shared.global [%0], [%1], 16, %2;"
                         :: "r"(dst), "l"(src), "r"(sz) : "memory");
        }
        asm volatile("cp.async.commit_group;" ::: "memory");
    };

    // fragment address components
    int a_r = wr * 32 + (lane & 15);
    uint32_t a_xm = (((uint32_t)a_r) & 7u) << 4;
    uint32_t a_kb = (uint32_t)((lane >> 4) * 16);   // koff bytes part
    int b_n = wc * 64 + ((lane >> 4) & 1) * 8 + (lane & 7);
    uint32_t b_xm = (((uint32_t)lane) & 7u) << 4;
    uint32_t b_kb = (uint32_t)(((lane >> 3) & 1) * 16);

    float acc[2][8][4];
#pragma unroll
    for (int mt = 0; mt < 2; mt++)
#pragma unroll
        for (int nt = 0; nt < 8; nt++)
#pragma unroll
            for (int e = 0; e < 4; e++) acc[mt][nt][e] = 0.f;

    load_stage(0, 0);
    for (int c = 0; c < 8; c++) {
        int p = c & 1;
        if (c + 1 < 8) {
            load_stage(c + 1, p ^ 1);
            asm volatile("cp.async.wait_group 1;" ::: "memory");
        } else {
            asm volatile("cp.async.wait_group 0;" ::: "memory");
        }
        __syncthreads();
        uint32_t stg = sb + SM_BUF + p * STAGESZ;
#pragma unroll
        for (int ks = 0; ks < 4; ks++) {
            uint32_t ka = (((uint32_t)(ks * 32)) + a_kb) ^ a_xm;
            uint32_t ah[2][4], al[2][4];
#pragma unroll
            for (int mt = 0; mt < 2; mt++) {
                uint32_t ad = stg + (uint32_t)((a_r + mt * 16) * 128) + ka;
                ldsm4(ah[mt], ad);
                ldsm4(al[mt], ad + MATSZ);
            }
            uint32_t kb2 = (((uint32_t)(ks * 32)) + b_kb) ^ b_xm;
            uint32_t bhf[4][4], blf[4][4];
#pragma unroll
            for (int ntp = 0; ntp < 4; ntp++) {
                uint32_t bd = stg + 2 * MATSZ + (uint32_t)((b_n + ntp * 16) * 128) + kb2;
                ldsm4(bhf[ntp], bd);
                ldsm4(blf[ntp], bd + MATSZ);
            }
#pragma unroll
            for (int mt = 0; mt < 2; mt++)
#pragma unroll
                for (int ntp = 0; ntp < 4; ntp++) {
                    mma_bf16(acc[mt][2 * ntp],     ah[mt], &bhf[ntp][0]);
                    mma_bf16(acc[mt][2 * ntp],     ah[mt], &blf[ntp][0]);
                    mma_bf16(acc[mt][2 * ntp],     al[mt], &bhf[ntp][0]);
                    mma_bf16(acc[mt][2 * ntp + 1], ah[mt], &bhf[ntp][2]);
                    mma_bf16(acc[mt][2 * ntp + 1], ah[mt], &blf[ntp][2]);
                    mma_bf16(acc[mt][2 * ntp + 1], al[mt], &bhf[ntp][2]);
                }
        }
        __syncthreads();
    }

    // ---- epilogue: exp once, stash e/x for column pass ----
    float* esm = (float*)(smem + SM_E);
    float* xsm = (float*)(smem + SM_X);
    int lr4 = lane >> 2;
    int lc2 = (lane & 3) * 2;
    float S[4], P[4], Cc[4];
    int rloc[4], rl[4];
#pragma unroll
    for (int q = 0; q < 4; q++) {
        int mt = q >> 1, h = q & 1;
        rloc[q] = wr * 32 + mt * 16 + h * 8 + lr4;
        rl[q] = lrow[rloc[q]];
        S[q] = P[q] = Cc[q] = 0.f;
    }
#pragma unroll
    for (int mt = 0; mt < 2; mt++)
#pragma unroll
        for (int nt = 0; nt < 8; nt++) {
            int cl0 = wc * 64 + nt * 8 + lc2;
            int c0l = lcol[cl0], c1l = lcol[cl0 + 1];
            int cg0 = col0 + cl0, cg1 = cg0 + 1;
#pragma unroll
            for (int h = 0; h < 2; h++) {
                int q = mt * 2 + h;
                int rg = row0 + rloc[q];
                float d0 = acc[mt][nt][h * 2 + 0], d1 = acc[mt][nt][h * 2 + 1];
                float x0 = (d0 - 1.0f) * INV_T, x1 = (d1 - 1.0f) * INV_T;
                float e0 = __expf(x0), e1 = __expf(x1);
                esm[rloc[q] * 132 + cl0]     = e0;
                esm[rloc[q] * 132 + cl0 + 1] = e1;
                xsm[rloc[q] * 132 + cl0]     = x0;
                xsm[rloc[q] * 132 + cl0 + 1] = x1;
                if (rg < HW) {
                    if (cg0 < HW && cg0 != rg) {
                        S[q] += e0;
                        if (c0l == rl[q]) { P[q] += x0; Cc[q] += 1.f; }
                    }
                    if (cg1 < HW && cg1 != rg) {
                        S[q] += e1;
                        if (c1l == rl[q]) { P[q] += x1; Cc[q] += 1.f; }
                    }
                }
            }
        }
#pragma unroll
    for (int q = 0; q < 4; q++) {
#pragma unroll
        for (int o = 1; o <= 2; o <<= 1) {
            S[q]  += __shfl_xor_sync(0xffffffffu, S[q], o);
            P[q]  += __shfl_xor_sync(0xffffffffu, P[q], o);
            Cc[q] += __shfl_xor_sync(0xffffffffu, Cc[q], o);
        }
    }
    if ((lane & 3) == 0) {
#pragma unroll
        for (int q = 0; q < 4; q++) {
            atomicAdd(&rowS[rloc[q]], S[q]);
            atomicAdd(&rowP[rloc[q]], P[q]);
            atomicAdd(&rowC[rloc[q]], Cc[q]);
        }
    }
    __syncthreads();
    if (tid < 128) {
        int rg = row0 + tid;
        if (rg < HW) {
            atomicAdd(&g_S[b * HW + rg], rowS[tid]);
            atomicAdd(&g_P[b * HW + rg], rowP[tid]);
            atomicAdd(&g_C[b * HW + rg], rowC[tid]);
        }
    }
    if (!diag) {
        int j = tid & 127, half = tid >> 7;
        int cg = col0 + j;
        if (cg < HW) {
            int cll = lcol[j];
            float S2 = 0.f, P2 = 0.f, C2 = 0.f;
            int rr0 = half * 64;
            for (int rr = rr0; rr < rr0 + 64; rr++) {
                int rg = row0 + rr;
                if (rg < HW && rg != cg) {
                    S2 += esm[rr * 132 + j];
                    if (lrow[rr] == cll) { P2 += xsm[rr * 132 + j]; C2 += 1.f; }
                }
            }
            atomicAdd(&g_S[b * HW + cg], S2);
            atomicAdd(&g_P[b * HW + cg], P2);
            atomicAdd(&g_C[b * HW + cg], C2);
        }
    }
}

// ---------------------------------------------------------------------------
// per-row supcon loss + per-image reduction
// ---------------------------------------------------------------------------
__global__ void supcon_row_kernel() {
    int b = blockIdx.x;
    int t = threadIdx.x;
    float s = 0.f, n = 0.f;
    for (int r = t; r < HW; r += 256) {
        float c = g_C[b * HW + r];
        if (c > 0.f) {
            s += -((g_P[b * HW + r] - c * logf(g_S[b * HW + r] + 1e-6f)) / c);
            n += 1.f;
        }
    }
    __shared__ float sS[256], sN[256];
    sS[t] = s; sN[t] = n;
    __syncthreads();
    for (int o = 128; o > 0; o >>= 1) {
        if (t < o) { sS[t] += sS[t + o]; sN[t] += sN[t + o]; }
        __syncthreads();
    }
    if (t == 0) { g_supcon_sum[b] = sS[0]; g_anchor_cnt[b] = sN[0]; }
}

// ---------------------------------------------------------------------------
// finalize
// ---------------------------------------------------------------------------
__global__ void finalize_kernel(const float* __restrict__ is_forged, float* __restrict__ out) {
    __shared__ float sc[BATCH], scv[BATCH], sp[BATCH], spv[BATCH], un[BATCH], unv[BATCH];
    int t = threadIdx.x;
    if (t < BATCH) {
        int b = t;
        float na = g_anchor_cnt[b];
        float supcon = g_supcon_sum[b] / fmaxf(na, 1.f);
        float supcon_valid = (na > 0.f) ? 1.f : 0.f;

        float cnt[NLBL], cn[NLBL], inv[NLBL];
#pragma unroll
        for (int l = 0; l < NLBL; l++) {
            cnt[l] = g_cnt[b][l];
            inv[l] = 1.f / fmaxf(cnt[l], 1.f);
            float s = 0.f;
            for (int d = 0; d < DIM; d++) {
                float m = g_label_sums[b][l][d] * inv[l];
                s += m * m;
            }
            cn[l] = s;
        }
        float terms = 0.f, npairs = 0.f;
        int npresent = 0;
#pragma unroll
        for (int l = 0; l < NLBL; l++) if (cnt[l] > 0.f) npresent++;
        for (int l1 = 0; l1 < NLBL; l1++) {
            for (int l2 = l1 + 1; l2 < NLBL; l2++) {
                if (cnt[l1] > 0.f && cnt[l2] > 0.f) {
                    float dot = 0.f;
                    for (int d = 0; d < DIM; d++)
                        dot += (g_label_sums[b][l1][d] * inv[l1]) *
                               (g_label_sums[b][l2][d] * inv[l2]);
                    float sq = cn[l1] + cn[l2] - 2.f * dot;
                    float dd = sqrtf(fmaxf(sq, 0.f));
                    terms += fmaxf(SEPM - dd, 0.f);
                    npairs += 1.f;
                }
            }
        }
        float sep = terms / fmaxf(npairs, 1.f);
        float sep_valid = (npresent >= 2) ? 1.f : 0.f;

        float uni, univ;
        if (is_forged[b] >= 0.5f) {
            float inst = 0.f, nl = 0.f;
#pragma unroll
            for (int l = 0; l < NLBL; l++) {
                float var = g_q[b][l] * inv[l] - cn[l];
                if (cnt[l] >= 2.f && var > UNITH) { inst += var - UNITH; nl += 1.f; }
            }
            uni = inst / fmaxf(nl, 1.f);
            univ = (nl > 0.f) ? 1.f : 0.f;
        } else {
            float qall = 0.f;
#pragma unroll
            for (int l = 0; l < NLBL; l++) qall += g_q[b][l];
            float nrm = 0.f;
            for (int d = 0; d < DIM; d++) {
                float s = 0.f;
#pragma unroll
                for (int l = 0; l < NLBL; l++) s += g_label_sums[b][l][d];
                s *= (1.f / (float)HW);
                nrm += s * s;
            }
            float var_all = qall * (1.f / (float)HW) - nrm;
            uni = (var_all > UNITH) ? (var_all - UNITH) : 0.f;
            univ = (var_all > UNITH) ? 1.f : 0.f;
        }

        sc[b] = supcon * supcon_valid; scv[b] = supcon_valid;
        sp[b] = sep * sep_valid;       spv[b] = sep_valid;
        un[b] = uni * univ;            unv[b] = univ;
    }
    __syncthreads();
    if (t == 0) {
        float a = 0.f, av = 0.f, s2 = 0.f, sv = 0.f, u = 0.f, uv = 0.f;
        for (int b = 0; b < BATCH; b++) {
            a += sc[b]; av += scv[b];
            s2 += sp[b]; sv += spv[b];
            u += un[b]; uv += unv[b];
        }
        float supcon = (av > 0.f) ? a / fmaxf(av, 1.f) : 0.f;
        float sep = (sv > 0.f) ? s2 / fmaxf(sv, 1.f) : 0.f;
        float uni = (uv > 0.f) ? u / fmaxf(uv, 1.f) : 0.f;
        out[0] = 1.0f * supcon + 0.5f * sep + 0.5f * uni;
    }
}

// ---------------------------------------------------------------------------
extern "C" void kernel_launch(void* const* d_in, const int* in_sizes, int n_in,
                              void* d_out, int out_size) {
    const float* emb   = (const float*)d_in[0];   // (16,33,33,512) f32
    const float* masks = (const float*)d_in[1];   // (16,6,33,33) f32
    const float* isf   = (const float*)d_in[2];   // (16,) f32
    float* out = (float*)d_out;

    cudaFuncSetAttribute(supcon_mma_kernel,
                         cudaFuncAttributeMaxDynamicSharedMemorySize, SM_TOTAL);

    zero_kernel<<<(BATCH * NLBL * DIM + 255) / 256, 256>>>();
    prep_kernel<<<BATCH * NMASK, 256>>>(masks);
    labels_kernel<<<(BATCH * HW + 255) / 256, 256>>>(masks);
    rn2_cvt_kernel<<<(BATCH * HW * 32 + 255) / 256, 256>>>(emb);
    centroid_kernel<<<dim3(CCH, BATCH), DIM>>>(emb);
    supcon_mma_kernel<<<dim3(NTILEPAIRS, BATCH), 256, SM_TOTAL>>>();
    supcon_row_kernel<<<BATCH, 256>>>();
    finalize_kernel<<<1, 32>>>(isf, out);
}